// round 15
// baseline (speedup 1.0000x reference)
#include <cuda_runtime.h>
#include <cstdint>

// KoopmanOperator: y_{t+1} = R(p(y_t)), 256 steps, y_0 = x[:,0,:]
//   h = tanh(y @ W1^T + b1);  p = h @ W2^T + b2
//   mu=p[2i], om=p[2i+1]; e=exp(dt*mu), c=cos(dt*om), s=sin(dt*om)
//   y'[2i] = e*(c*y0 - s*y1);  y'[2i+1] = e*(s*y0 - c*y1)   (per reference)
//
// R14 warp-specialized design (2 cols/thread, register weights, named-barrier
// producer/consumer pairs), halved per CTA: 16 rows, 128 threads, 2 pairs.
// 256 CTAs -> 2 barrier-independent CTAs per loaded SM = 2 pipelines/SMSP,
// filling the ~1600 cyc/step of exposed latency measured in R14.
// P2 additionally carries its (y0,y1) pair in registers across steps.

#define D 64
#define T_STEPS 256
#define ROWS_PER_CTA 16
#define THREADS 128
#define NCTA 256
#define STRIDE 68               // floats; 272B pitch
#define DT 0.01f

__device__ __forceinline__ void fma2(unsigned long long& d,
                                     unsigned long long a,
                                     unsigned long long b) {
    asm("fma.rn.f32x2 %0, %1, %2, %0;" : "+l"(d) : "l"(a), "l"(b));
}
__device__ __forceinline__ unsigned long long pack2(float x, float y) {
    unsigned long long u;
    asm("mov.b64 %0, {%1, %2};" : "=l"(u) : "f"(x), "f"(y));
    return u;
}
__device__ __forceinline__ float2 unpack2(unsigned long long u) {
    float2 f;
    asm("mov.b64 {%0, %1}, %2;" : "=f"(f.x), "=f"(f.y) : "l"(u));
    return f;
}

// Accurate fast tanh (~1e-6): EX2 + RCP.
__device__ __forceinline__ float tanh_acc(float x) {
    float ax = fabsf(x);
    float e  = __expf(-2.0f * ax);
    float t  = __fdividef(1.0f - e, 1.0f + e);
    return copysignf(t, x);
}
// Small-argument Taylor (|z| <~ 0.3): error < 1e-7, pure FFMA.
__device__ __forceinline__ float exp_small(float z) {
    float p = fmaf(z, 1.0f / 120.0f, 1.0f / 24.0f);
    p = fmaf(z, p, 1.0f / 6.0f);
    p = fmaf(z, p, 0.5f);
    p = fmaf(z, p, 1.0f);
    return fmaf(z, p, 1.0f);
}
__device__ __forceinline__ float cos_small(float z2) {
    float p = fmaf(z2, -1.0f / 720.0f, 1.0f / 24.0f);
    p = fmaf(z2, p, -0.5f);
    return fmaf(z2, p, 1.0f);
}
__device__ __forceinline__ float sin_small(float z, float z2) {
    float p = fmaf(z2, 1.0f / 120.0f, -1.0f / 6.0f);
    return z * fmaf(z2, p, 1.0f);
}

// 4 rows x 2 register-resident weight columns. Broadcast src loads.
// Per k-chunk: 4 LDS.128 feed 16 FFMA2.
__device__ __forceinline__ void gemv4x2(const unsigned long long (&wa)[32],
                                        const unsigned long long (&wb)[32],
                                        const float* __restrict__ src,
                                        int r0, float bA, float bB,
                                        float o[4][2]) {
    unsigned long long acc[4][2];
#pragma unroll
    for (int i = 0; i < 4; i++) {
        acc[i][0] = pack2(bA, 0.0f);
        acc[i][1] = pack2(bB, 0.0f);
    }
#pragma unroll
    for (int kc = 0; kc < D; kc += 4) {
        ulonglong2 v[4];
#pragma unroll
        for (int i = 0; i < 4; i++)
            v[i] = *reinterpret_cast<const ulonglong2*>(src + (r0 + i) * STRIDE + kc);
        const unsigned long long alo = wa[kc >> 1], ahi = wa[(kc >> 1) + 1];
        const unsigned long long blo = wb[kc >> 1], bhi = wb[(kc >> 1) + 1];
#pragma unroll
        for (int i = 0; i < 4; i++) {
            fma2(acc[i][0], alo, v[i].x);
            fma2(acc[i][1], blo, v[i].x);
        }
#pragma unroll
        for (int i = 0; i < 4; i++) {
            fma2(acc[i][0], ahi, v[i].y);
            fma2(acc[i][1], bhi, v[i].y);
        }
    }
#pragma unroll
    for (int i = 0; i < 4; i++) {
#pragma unroll
        for (int c = 0; c < 2; c++) {
            float2 f = unpack2(acc[i][c]);
            o[i][c] = f.x + f.y;
        }
    }
}

__global__ void __launch_bounds__(THREADS, 2)
koopman_kernel(const float* __restrict__ x,
               const float* __restrict__ W1g,
               const float* __restrict__ b1g,
               const float* __restrict__ W2g,
               const float* __restrict__ b2g,
               float* __restrict__ out) {
    __shared__ float Ys[ROWS_PER_CTA * STRIDE];
    __shared__ float Hs[ROWS_PER_CTA * STRIDE];

    const int tid  = threadIdx.x;
    const int w    = tid >> 5;
    const int lane = tid & 31;
    const bool isP1 = (w < 2);
    const int p    = isP1 ? w : (w - 2);     // pair 0..1: warps (p, p+2)
    const int bar  = 1 + p;                  // named barrier per pair
    const int rA   = 8 * p;                  // block A rows [rA, rA+4)
    const int rB   = 8 * p + 4;              // block B rows [rB, rB+4)
    const int rowbase = blockIdx.x * ROWS_PER_CTA;

    // ---- y0 -> smem (all threads) ----
    for (int i = tid; i < ROWS_PER_CTA * D; i += THREADS) {
        int r = i >> 6, k = i & 63;
        Ys[r * STRIDE + k] = x[(size_t)(rowbase + r) * (T_STEPS * D) + k];
    }

#define BARP() asm volatile("bar.sync %0, 64;" :: "r"(bar) : "memory")

    if (isP1) {
        // ======== P1: GEMV1 + tanh producer ========
        const int cA = lane, cB = lane + 32;
        unsigned long long wa[32], wb[32];
#pragma unroll
        for (int kc = 0; kc < D; kc += 4) {
            float4 a = *reinterpret_cast<const float4*>(W1g + cA * D + kc);
            float4 b = *reinterpret_cast<const float4*>(W1g + cB * D + kc);
            wa[kc >> 1]       = pack2(a.x, a.y);
            wa[(kc >> 1) + 1] = pack2(a.z, a.w);
            wb[kc >> 1]       = pack2(b.x, b.y);
            wb[(kc >> 1) + 1] = pack2(b.z, b.w);
        }
        const float bA = b1g[cA], bB = b1g[cB];
        __syncthreads();                      // Ys init visible

        float o[4][2];
        // prologue: H(A, t=0)
        gemv4x2(wa, wb, Ys, rA, bA, bB, o);
#pragma unroll
        for (int i = 0; i < 4; i++) {
            Hs[(rA + i) * STRIDE + cA] = tanh_acc(o[i][0]);
            Hs[(rA + i) * STRIDE + cB] = tanh_acc(o[i][1]);
        }
        BARP();

#pragma unroll 1
        for (int t = 0; t < T_STEPS; t++) {
            // PhaseA: G1(B, t)
            gemv4x2(wa, wb, Ys, rB, bA, bB, o);
#pragma unroll
            for (int i = 0; i < 4; i++) {
                Hs[(rB + i) * STRIDE + cA] = tanh_acc(o[i][0]);
                Hs[(rB + i) * STRIDE + cB] = tanh_acc(o[i][1]);
            }
            BARP();
            // PhaseB: G1(A, t+1)  (skip on last step)
            if (t < T_STEPS - 1) {
                gemv4x2(wa, wb, Ys, rA, bA, bB, o);
#pragma unroll
                for (int i = 0; i < 4; i++) {
                    Hs[(rA + i) * STRIDE + cA] = tanh_acc(o[i][0]);
                    Hs[(rA + i) * STRIDE + cB] = tanh_acc(o[i][1]);
                }
            }
            BARP();
        }
    } else {
        // ======== P2: GEMV2 + rotation-update consumer ========
        const int j0 = 2 * lane, j1 = j0 + 1;
        unsigned long long wa[32], wb[32];
#pragma unroll
        for (int kc = 0; kc < D; kc += 4) {
            float4 a = *reinterpret_cast<const float4*>(W2g + j0 * D + kc);
            float4 b = *reinterpret_cast<const float4*>(W2g + j1 * D + kc);
            wa[kc >> 1]       = pack2(a.x, a.y);
            wa[(kc >> 1) + 1] = pack2(a.z, a.w);
            wb[kc >> 1]       = pack2(b.x, b.y);
            wb[(kc >> 1) + 1] = pack2(b.z, b.w);
        }
        const float bA = b2g[j0], bB = b2g[j1];
        __syncthreads();                      // Ys init visible

        // carry this thread's (y0,y1) pairs in registers across all steps
        float2 yA[4], yB[4];
#pragma unroll
        for (int i = 0; i < 4; i++) {
            yA[i] = *reinterpret_cast<const float2*>(Ys + (rA + i) * STRIDE + j0);
            yB[i] = *reinterpret_cast<const float2*>(Ys + (rB + i) * STRIDE + j0);
        }

        float o[4][2];
        BARP();                               // matches P1 prologue barrier

        auto g2_update = [&](int r0, float2 (&yr)[4], int t) {
            gemv4x2(wa, wb, Hs, r0, bA, bB, o);
#pragma unroll
            for (int i = 0; i < 4; i++) {
                const int r = r0 + i;
                float e  = exp_small(DT * o[i][0]);
                float z  = DT * o[i][1], z2 = z * z;
                float c  = cos_small(z2);
                float s  = sin_small(z, z2);
                float n0 = e * (c * yr[i].x - s * yr[i].y);
                float n1 = e * (s * yr[i].x - c * yr[i].y);  // ref: s*y0 - c*y1
                yr[i] = make_float2(n0, n1);
                *reinterpret_cast<float2*>(Ys + r * STRIDE + j0) = yr[i];
                const size_t ob = ((size_t)(rowbase + r) * T_STEPS + t) * D + j0;
                *reinterpret_cast<float2*>(out + ob) = yr[i];
            }
        };

#pragma unroll 1
        for (int t = 0; t < T_STEPS; t++) {
            // PhaseA: G2(A, t)  (Hs(A) from P1's previous phase)
            g2_update(rA, yA, t);
            BARP();
            // PhaseB: G2(B, t)  (Hs(B) from P1's PhaseA)
            g2_update(rB, yB, t);
            BARP();
        }
    }
#undef BARP
}

extern "C" void kernel_launch(void* const* d_in, const int* in_sizes, int n_in,
                              void* d_out, int out_size) {
    const float* x  = (const float*)d_in[0];
    const float* W1 = (const float*)d_in[1];
    const float* b1 = (const float*)d_in[2];
    const float* W2 = (const float*)d_in[3];
    const float* b2 = (const float*)d_in[4];
    float* out = (float*)d_out;

    // 4096 rows / 16 per CTA = 256 CTAs; 2 CTAs per loaded SM.
    koopman_kernel<<<NCTA, THREADS>>>(x, W1, b1, W2, b2, out);
}